// round 10
// baseline (speedup 1.0000x reference)
#include <cuda_runtime.h>
#include <cstdint>

typedef unsigned long long u64;

// ---------------------------------------------------------------------------
// BinaryNet forward, fully bitwise. R10: single kernel (tables built per block),
// warp-pair image split (A: rows0-10/conv1 q0-4/conv2 R0-1; B: rows8-14/q4-6/
// conv2 R2 + conv3 + fc) -> 2x warp count for latency hiding.
// ---------------------------------------------------------------------------

__device__ __forceinline__ void conv2pix(const u64* sT, uint32_t q0, uint32_t q1,
                                         uint32_t q2, int C,
                                         uint32_t& vbt, uint32_t& mbt) {
    uint32_t r0 = (q0 >> (8 * C)) & 0xFFFu;
    uint32_t r1 = (q1 >> (8 * C)) & 0xFFFu;
    uint32_t r2 = (q2 >> (8 * C)) & 0xFFFu;
    u64 d8 = sT[r0 & 63] + sT[64 + (r0 >> 6)]
           + sT[128 + (r1 & 63)] + sT[192 + (r1 >> 6)]
           + sT[256 + (r2 & 63)] + sT[320 + (r2 >> 6)];
    uint32_t dlo = (uint32_t)d8, dhi = (uint32_t)(d8 >> 32);
    // per-byte d in [0,36]: bit7(d+110) <=> d>=18 ; bit7(d+109) <=> d>=19
    uint32_t a18l = dlo + 0x6E6E6E6Eu, a18h = dhi + 0x6E6E6E6Eu;
    uint32_t a19l = dlo + 0x6D6D6D6Du, a19h = dhi + 0x6D6D6D6Du;
    uint32_t vl = (~a18l) & 0x80808080u;            // d<18  (sum>0)
    uint32_t vh = (~a18h) & 0x80808080u;
    uint32_t ml = ((~a18l) | a19l) & 0x80808080u;   // d!=18 (sum!=0)
    uint32_t mh = ((~a18h) | a19h) & 0x80808080u;
    vbt = ((vl * 0x00204081u) >> 28) | (((vh * 0x00204081u) >> 28) << 4);
    mbt = ((ml * 0x00204081u) >> 28) | (((mh * 0x00204081u) >> 28) << 4);
}

__global__ __launch_bounds__(256, 6) void bnn_kernel(const float* __restrict__ x,
                                                     const float* __restrict__ w1,
                                                     const float* __restrict__ w2,
                                                     const float* __restrict__ w3,
                                                     const float* __restrict__ wfc1,
                                                     const float* __restrict__ wfc2,
                                                     float* __restrict__ out, int B) {
    // 256 threads = 8 warps; 128 images/block. Warps 0-3: role A, 4-7: role B.
    __shared__ uint32_t sbits[901];               // 128 img * 225 bits = 900 words + pad
    __shared__ uint32_t s_w1p[4];
    __shared__ u64      s_w2p[8];
    __shared__ uint32_t s_lut1w[128];             // 512B conv1 LUT
    __shared__ u64      sT[384];                  // conv2 row LUTs
    __shared__ uint32_t s_w3a[16], s_w3b[16], s_w3c[16];
    __shared__ uint32_t s_wfc1[8];
    __shared__ uint32_t s_wfc2;
    __shared__ uint32_t s_hv[4][128];             // A->B handoff, conflict-free

    const int tid  = threadIdx.x;
    const int wrp  = tid >> 5;
    const int lane = tid & 31;

    // --- 1. raw weight packs (small serial loops; hidden across blocks) ---
    if (tid < 4) {
        uint32_t p = 0;
        for (int k = 0; k < 9; k++) p |= (uint32_t)(w1[tid * 9 + k] > 0.0f) << k;
        s_w1p[tid] = p;
    }
    if (tid < 8) {
        u64 p = 0;
        for (int ic = 0; ic < 4; ic++)
            for (int k = 0; k < 9; k++)
                p |= (u64)(w2[(tid * 4 + ic) * 9 + k] > 0.0f) << (k * 4 + ic);
        s_w2p[tid] = p;
        uint32_t qv = 0;
        for (int j = 0; j < 16; j++) qv |= (uint32_t)(wfc1[tid * 16 + j] > 0.0f) << j;
        s_wfc1[tid] = qv;
    }
    if (tid < 16) {   // conv3 weights, pixel-major: bit (pix*8 + ic)
        uint32_t a = 0, b = 0, c = 0;
        for (int ic = 0; ic < 8; ic++)
            for (int pix = 0; pix < 9; pix++) {
                uint32_t bit = (uint32_t)(w3[(tid * 8 + ic) * 9 + pix] > 0.0f);
                if (pix < 4)      a |= bit << (pix * 8 + ic);
                else if (pix < 8) b |= bit << ((pix - 4) * 8 + ic);
                else              c |= bit << ic;
            }
        s_w3a[tid] = a; s_w3b[tid] = b; s_w3c[tid] = c;
    }
    if (tid == 0) {
        uint32_t p = 0;
        for (int j = 0; j < 8; j++) p |= (uint32_t)(wfc2[j] > 0.0f) << j;
        s_wfc2 = p;
    }

    // --- 2. coalesced load + ballot binarization: 900 words, ~113/warp ---
    const int blockBase = blockIdx.x * (128 * 225);
    const int total     = B * 225;
    {
        const int wstart = wrp * 113;
        int n = 900 - wstart; if (n > 113) n = 113;
        if (blockBase + 900 * 32 <= total) {
            #pragma unroll 8
            for (int k = 0; k < n; k++) {
                int j = wstart + k;
                float v = __ldg(x + blockBase + (j << 5) + lane);
                uint32_t b = __ballot_sync(0xFFFFFFFFu, v > 0.0f);
                if (lane == 0) sbits[j] = b;
            }
        } else {
            for (int k = 0; k < n; k++) {
                int j   = wstart + k;
                int idx = blockBase + (j << 5) + lane;
                float v = (idx < total) ? __ldg(x + idx) : 0.0f;
                uint32_t b = __ballot_sync(0xFFFFFFFFu, v > 0.0f);
                if (lane == 0) sbits[j] = b;
            }
        }
    }
    __syncthreads();   // raw packs + bitstream complete

    // --- 3. table builds (need s_w1p/s_w2p) ---
    {
        uint32_t wa = s_w1p[0], wb2 = s_w1p[1], wc = s_w1p[2], wd = s_w1p[3];
        #pragma unroll
        for (int e = tid; e < 512; e += 256) {
            uint32_t nib =  (uint32_t)(__popc((uint32_t)e ^ wa)  <= 4)
                         | ((uint32_t)(__popc((uint32_t)e ^ wb2) <= 4) << 1)
                         | ((uint32_t)(__popc((uint32_t)e ^ wc)  <= 4) << 2)
                         | ((uint32_t)(__popc((uint32_t)e ^ wd)  <= 4) << 3);
            ((uint8_t*)s_lut1w)[e] = (uint8_t)nib;
        }
    }
    for (int t = tid; t < 384; t += 256) {
        int tab = t >> 6, e = t & 63;
        int sh  = (tab >> 1) * 12 + (tab & 1) * 6;
        u64 val = 0;
        #pragma unroll
        for (int o = 0; o < 8; o++)
            val |= (u64)__popc((uint32_t)e ^ (uint32_t)((s_w2p[o] >> sh) & 63)) << (8 * o);
        sT[t] = val;
    }
    __syncthreads();   // tables ready

    // --- 4. role phases ---
    const uint8_t* lut1 = (const uint8_t*)s_lut1w;
    const bool isA = (wrp < 4);
    const int  grp = isA ? wrp : wrp - 4;
    const int  i   = grp * 32 + lane;       // image index within block
    const int  base = i * 225;

    uint32_t v2b = 0, m2b = 0, v2c = 0, m2c = 0;   // carried across sync by B

    if (isA) {
        // rows 0..10 -> q0..q4 -> conv2 R=0,1 (pixels 0..5)
        uint32_t rows[11];
        #pragma unroll
        for (int r = 0; r < 11; r++) {
            int off = base + 15 * r;
            rows[r] = __funnelshift_r(sbits[off >> 5], sbits[(off >> 5) + 1], off & 31) & 0x7FFFu;
        }
        uint32_t q[5];
        #pragma unroll
        for (int orow = 0; orow < 5; orow++) {
            uint32_t r0 = rows[2 * orow], r1 = rows[2 * orow + 1], r2 = rows[2 * orow + 2];
            uint32_t acc = 0;
            #pragma unroll
            for (int oc = 0; oc < 7; oc++) {
                uint32_t patch = ((r0 >> (2 * oc)) & 7u)
                               | (((r1 >> (2 * oc)) & 7u) << 3)
                               | (((r2 >> (2 * oc)) & 7u) << 6);
                acc |= (uint32_t)lut1[patch] << (4 * oc);
            }
            q[orow] = acc;
        }
        uint32_t v2a = 0, m2a = 0, v2bA = 0, m2bA = 0;
        #pragma unroll
        for (int R = 0; R < 2; R++) {
            #pragma unroll
            for (int C = 0; C < 3; C++) {
                uint32_t vbt, mbt;
                conv2pix(sT, q[2 * R], q[2 * R + 1], q[2 * R + 2], C, vbt, mbt);
                const int pix = R * 3 + C;
                if (pix < 4) { v2a  |= vbt << (8 * pix);       m2a  |= mbt << (8 * pix); }
                else         { v2bA |= vbt << (8 * (pix - 4)); m2bA |= mbt << (8 * (pix - 4)); }
            }
        }
        s_hv[0][i] = v2a; s_hv[1][i] = m2a; s_hv[2][i] = v2bA; s_hv[3][i] = m2bA;
    } else {
        // rows 8..14 -> q4..q6 -> conv2 R=2 (pixels 6..8)
        uint32_t rows[7];
        #pragma unroll
        for (int r = 0; r < 7; r++) {
            int off = base + 15 * (r + 8);
            rows[r] = __funnelshift_r(sbits[off >> 5], sbits[(off >> 5) + 1], off & 31) & 0x7FFFu;
        }
        uint32_t q[3];
        #pragma unroll
        for (int orow = 0; orow < 3; orow++) {
            uint32_t r0 = rows[2 * orow], r1 = rows[2 * orow + 1], r2 = rows[2 * orow + 2];
            uint32_t acc = 0;
            #pragma unroll
            for (int oc = 0; oc < 7; oc++) {
                uint32_t patch = ((r0 >> (2 * oc)) & 7u)
                               | (((r1 >> (2 * oc)) & 7u) << 3)
                               | (((r2 >> (2 * oc)) & 7u) << 6);
                acc |= (uint32_t)lut1[patch] << (4 * oc);
            }
            q[orow] = acc;
        }
        #pragma unroll
        for (int C = 0; C < 3; C++) {
            uint32_t vbt, mbt;
            conv2pix(sT, q[0], q[1], q[2], C, vbt, mbt);
            const int pix = 6 + C;
            if (pix < 8) { v2b |= vbt << (8 * (pix - 4)); m2b |= mbt << (8 * (pix - 4)); }
            else         { v2c = vbt; m2c = mbt; }
        }
    }
    __syncthreads();   // handoff visible

    if (!isA) {
        uint32_t v2a = s_hv[0][i], m2a = s_hv[1][i];
        v2b |= s_hv[2][i];  m2b |= s_hv[3][i];

        // --- conv3: 16 channels, ternary ---
        const int mc2 = __popc(m2a) + __popc(m2b) + __popc(m2c);
        uint32_t v3 = 0, m3 = 0;
        #pragma unroll
        for (int o = 0; o < 16; o++) {
            int d = __popc(m2a & (v2a ^ s_w3a[o]))
                  + __popc(m2b & (v2b ^ s_w3b[o]))
                  + __popc(m2c & (v2c ^ s_w3c[o]));
            int s = mc2 - 2 * d;
            v3 |= (uint32_t)(s > 0)  << o;
            m3 |= (uint32_t)(s != 0) << o;
        }

        // --- fc1: 16 -> 8, ternary ---
        const int mc3 = __popc(m3);
        uint32_t v4 = 0, m4 = 0;
        #pragma unroll
        for (int o = 0; o < 8; o++) {
            int d = __popc(m3 & (v3 ^ s_wfc1[o]));
            int s = mc3 - 2 * d;
            v4 |= (uint32_t)(s > 0)  << o;
            m4 |= (uint32_t)(s != 0) << o;
        }

        // --- fc2: 8 -> 1, integer output ---
        int d5  = __popc(m4 & (v4 ^ s_wfc2));
        int res = __popc(m4) - 2 * d5;

        const int img = blockIdx.x * 128 + i;
        if (img < B) out[img] = (float)res;
    }
}

extern "C" void kernel_launch(void* const* d_in, const int* in_sizes, int n_in,
                              void* d_out, int out_size) {
    const float* x    = (const float*)d_in[0];
    const float* w1   = (const float*)d_in[1];
    const float* w2   = (const float*)d_in[2];
    const float* w3   = (const float*)d_in[3];
    const float* wfc1 = (const float*)d_in[4];
    const float* wfc2 = (const float*)d_in[5];
    float* out = (float*)d_out;

    int B = in_sizes[0] / 225;                 // x is [B,1,15,15]
    int blocks = (B + 127) / 128;              // 128 images / block, 8 warps
    bnn_kernel<<<blocks, 256>>>(x, w1, w2, w3, wfc1, wfc2, out, B);
}

// round 11
// speedup vs baseline: 1.4389x; 1.4389x over previous
#include <cuda_runtime.h>
#include <cstdint>

typedef unsigned long long u64;

// ---------------------------------------------------------------------------
// BinaryNet forward, fully bitwise. R11: single fused kernel. Per-warp table
// construction (shfl broadcasts, no barriers) hidden behind a software-
// pipelined ballot-load of the input bitstream; one __syncthreads; then the
// R9 compute path (conv1 LUT, conv2 6-bit row LUTs + byte-SIMD, conv3/fc
// ternary popcount).
// ---------------------------------------------------------------------------

__global__ __launch_bounds__(128, 7) void bnn_kernel(const float* __restrict__ x,
                                                     const float* __restrict__ w1,
                                                     const float* __restrict__ w2,
                                                     const float* __restrict__ w3,
                                                     const float* __restrict__ wfc1,
                                                     const float* __restrict__ wfc2,
                                                     float* __restrict__ out, int B) {
    // 128 threads = 4 warps, 1 image/thread, warp-local bitstreams.
    __shared__ uint32_t sbits[4][226];     // 32 img * 225 bits = 225 words + pad
    __shared__ uint32_t s_lut1w[128];      // 512B conv1 LUT (9-bit patch -> 4 ch bits)
    __shared__ u64      sT[384];           // conv2 row LUTs [(r*2+h)*64+e], byte o = popc6
    __shared__ uint32_t s_w3a[16], s_w3b[16], s_w3c[16];
    __shared__ uint32_t s_wfc1[8];
    __shared__ uint32_t s_wfc2;

    const int tid  = threadIdx.x;
    const int wrp  = tid >> 5;
    const int lane = tid & 31;

    // ---- Phase 0: warp-local table construction (no block barriers) ----
    if (wrp == 0) {
        // lanes 0-3 pack w1 channels, broadcast, all lanes build conv1 LUT
        uint32_t p = 0;
        if (lane < 4) {
            #pragma unroll
            for (int k = 0; k < 9; k++) p |= (uint32_t)(w1[lane * 9 + k] > 0.0f) << k;
        }
        uint32_t wa = __shfl_sync(0xFFFFFFFFu, p, 0);
        uint32_t wb = __shfl_sync(0xFFFFFFFFu, p, 1);
        uint32_t wc = __shfl_sync(0xFFFFFFFFu, p, 2);
        uint32_t wd = __shfl_sync(0xFFFFFFFFu, p, 3);
        #pragma unroll
        for (int e = lane; e < 512; e += 32) {
            uint32_t nib =  (uint32_t)(__popc((uint32_t)e ^ wa) <= 4)
                         | ((uint32_t)(__popc((uint32_t)e ^ wb) <= 4) << 1)
                         | ((uint32_t)(__popc((uint32_t)e ^ wc) <= 4) << 2)
                         | ((uint32_t)(__popc((uint32_t)e ^ wd) <= 4) << 3);
            ((uint8_t*)s_lut1w)[e] = (uint8_t)nib;
        }
    } else if (wrp == 1) {
        // lanes 0-7 pack w2 output channels, broadcast 8x u64, build conv2 LUTs
        u64 p = 0;
        if (lane < 8) {
            for (int ic = 0; ic < 4; ic++)
                #pragma unroll
                for (int k = 0; k < 9; k++)
                    p |= (u64)(w2[(lane * 4 + ic) * 9 + k] > 0.0f) << (k * 4 + ic);
        }
        uint32_t plo = (uint32_t)p, phi = (uint32_t)(p >> 32);
        u64 w2r[8];
        #pragma unroll
        for (int o = 0; o < 8; o++) {
            uint32_t lo = __shfl_sync(0xFFFFFFFFu, plo, o);
            uint32_t hi = __shfl_sync(0xFFFFFFFFu, phi, o);
            w2r[o] = ((u64)hi << 32) | lo;
        }
        #pragma unroll
        for (int t = lane; t < 384; t += 32) {
            int tab = t >> 6, e = t & 63;
            int sh  = (tab >> 1) * 12 + (tab & 1) * 6;
            u64 val = 0;
            #pragma unroll
            for (int o = 0; o < 8; o++)
                val |= (u64)__popc((uint32_t)e ^ (uint32_t)((w2r[o] >> sh) & 63)) << (8 * o);
            sT[t] = val;
        }
    } else if (wrp == 2) {
        if (lane < 16) {       // conv3 weights, pixel-major: bit (pix*8 + ic)
            uint32_t a = 0, b = 0, c = 0;
            for (int ic = 0; ic < 8; ic++)
                #pragma unroll
                for (int pix = 0; pix < 9; pix++) {
                    uint32_t bit = (uint32_t)(w3[(lane * 8 + ic) * 9 + pix] > 0.0f);
                    if (pix < 4)      a |= bit << (pix * 8 + ic);
                    else if (pix < 8) b |= bit << ((pix - 4) * 8 + ic);
                    else              c |= bit << ic;
                }
            s_w3a[lane] = a; s_w3b[lane] = b; s_w3c[lane] = c;
        } else if (lane < 24) { // fc1 rows
            int o = lane - 16;
            uint32_t qv = 0;
            #pragma unroll
            for (int j = 0; j < 16; j++) qv |= (uint32_t)(wfc1[o * 16 + j] > 0.0f) << j;
            s_wfc1[o] = qv;
        } else if (lane == 24) {
            uint32_t pp = 0;
            #pragma unroll
            for (int j = 0; j < 8; j++) pp |= (uint32_t)(wfc2[j] > 0.0f) << j;
            s_wfc2 = pp;
        }
    }

    // ---- Phase 1: software-pipelined coalesced load + ballot binarization ----
    // 225 words/warp = 28 chunks of 8 + 1 tail word.
    const int warpBase = blockIdx.x * (128 * 225) + wrp * (32 * 225);
    const int total    = B * 225;
    uint32_t* wb = sbits[wrp];

    if (warpBase + 225 * 32 <= total) {
        const float* xp = x + warpBase + lane;
        float c0[8], c1[8];
        #pragma unroll
        for (int j = 0; j < 8; j++) c0[j] = __ldg(xp + 32 * j);
        #pragma unroll
        for (int j = 0; j < 8; j++) c1[j] = __ldg(xp + 256 + 32 * j);

        #pragma unroll 1
        for (int c = 0; c < 26; c += 2) {
            // ballots for chunk c (c0), then refill c0 with chunk c+2
            #pragma unroll
            for (int j = 0; j < 8; j++) {
                uint32_t b = __ballot_sync(0xFFFFFFFFu, c0[j] > 0.0f);
                if (lane == 0) wb[c * 8 + j] = b;
            }
            #pragma unroll
            for (int j = 0; j < 8; j++) c0[j] = __ldg(xp + (c + 2) * 256 + 32 * j);
            // ballots for chunk c+1 (c1), then refill c1 with chunk c+3
            #pragma unroll
            for (int j = 0; j < 8; j++) {
                uint32_t b = __ballot_sync(0xFFFFFFFFu, c1[j] > 0.0f);
                if (lane == 0) wb[(c + 1) * 8 + j] = b;
            }
            #pragma unroll
            for (int j = 0; j < 8; j++) c1[j] = __ldg(xp + (c + 3) * 256 + 32 * j);
        }
        // chunks 26, 27 (already in c0/c1)
        #pragma unroll
        for (int j = 0; j < 8; j++) {
            uint32_t b = __ballot_sync(0xFFFFFFFFu, c0[j] > 0.0f);
            if (lane == 0) wb[26 * 8 + j] = b;
        }
        #pragma unroll
        for (int j = 0; j < 8; j++) {
            uint32_t b = __ballot_sync(0xFFFFFFFFu, c1[j] > 0.0f);
            if (lane == 0) wb[27 * 8 + j] = b;
        }
        // word 224
        {
            float v = __ldg(xp + 224 * 32);
            uint32_t b = __ballot_sync(0xFFFFFFFFu, v > 0.0f);
            if (lane == 0) wb[224] = b;
        }
    } else {
        for (int k = 0; k < 225; k++) {
            int idx = warpBase + k * 32 + lane;
            float v = (idx < total) ? __ldg(x + idx) : 0.0f;
            uint32_t b = __ballot_sync(0xFFFFFFFFu, v > 0.0f);
            if (lane == 0) wb[k] = b;
        }
    }

    __syncthreads();   // tables + own bitstream visible

    // ---- Phase 2: compute (R9 path) ----
    const uint8_t* lut1 = (const uint8_t*)s_lut1w;
    const int base = lane * 225;

    // extract 15 rows of 15 bits
    uint32_t rows[15];
    #pragma unroll
    for (int r = 0; r < 15; r++) {
        int off = base + r * 15;
        rows[r] = __funnelshift_r(wb[off >> 5], wb[(off >> 5) + 1], off & 31) & 0x7FFFu;
    }

    // conv1: 7x7, 4 channels, nibble-packed rows
    uint32_t q[7];
    #pragma unroll
    for (int orow = 0; orow < 7; orow++) {
        uint32_t r0 = rows[2 * orow], r1 = rows[2 * orow + 1], r2 = rows[2 * orow + 2];
        uint32_t acc = 0;
        #pragma unroll
        for (int oc = 0; oc < 7; oc++) {
            uint32_t patch = ((r0 >> (2 * oc)) & 7u)
                           | (((r1 >> (2 * oc)) & 7u) << 3)
                           | (((r2 >> (2 * oc)) & 7u) << 6);
            acc |= (uint32_t)lut1[patch] << (4 * oc);
        }
        q[orow] = acc;
    }

    // conv2: 3x3, 8 channels, ternary; 6-bit row LUTs + byte-SIMD compares
    uint32_t v2a = 0, v2b = 0, v2c = 0, m2a = 0, m2b = 0, m2c = 0;
    #pragma unroll
    for (int R = 0; R < 3; R++) {
        uint32_t q0 = q[2 * R], q1 = q[2 * R + 1], q2 = q[2 * R + 2];
        #pragma unroll
        for (int C = 0; C < 3; C++) {
            uint32_t r0 = (q0 >> (8 * C)) & 0xFFFu;
            uint32_t r1 = (q1 >> (8 * C)) & 0xFFFu;
            uint32_t r2 = (q2 >> (8 * C)) & 0xFFFu;
            u64 d8 = sT[r0 & 63] + sT[64 + (r0 >> 6)]
                   + sT[128 + (r1 & 63)] + sT[192 + (r1 >> 6)]
                   + sT[256 + (r2 & 63)] + sT[320 + (r2 >> 6)];
            uint32_t dlo = (uint32_t)d8, dhi = (uint32_t)(d8 >> 32);
            // per-byte d in [0,36]: bit7(d+110) <=> d>=18 ; bit7(d+109) <=> d>=19
            uint32_t a18l = dlo + 0x6E6E6E6Eu, a18h = dhi + 0x6E6E6E6Eu;
            uint32_t a19l = dlo + 0x6D6D6D6Du, a19h = dhi + 0x6D6D6D6Du;
            uint32_t vl = (~a18l) & 0x80808080u;            // d<18  (sum>0)
            uint32_t vh = (~a18h) & 0x80808080u;
            uint32_t ml = ((~a18l) | a19l) & 0x80808080u;   // d!=18 (sum!=0)
            uint32_t mh = ((~a18h) | a19h) & 0x80808080u;
            uint32_t vbt = ((vl * 0x00204081u) >> 28) | (((vh * 0x00204081u) >> 28) << 4);
            uint32_t mbt = ((ml * 0x00204081u) >> 28) | (((mh * 0x00204081u) >> 28) << 4);
            const int pix = R * 3 + C;
            if (pix < 4)      { v2a |= vbt << (8 * pix);       m2a |= mbt << (8 * pix); }
            else if (pix < 8) { v2b |= vbt << (8 * (pix - 4)); m2b |= mbt << (8 * (pix - 4)); }
            else              { v2c = vbt;                     m2c = mbt; }
        }
    }

    // conv3: 16 channels, ternary
    const int mc2 = __popc(m2a) + __popc(m2b) + __popc(m2c);
    uint32_t v3 = 0, m3 = 0;
    #pragma unroll
    for (int o = 0; o < 16; o++) {
        int d = __popc(m2a & (v2a ^ s_w3a[o]))
              + __popc(m2b & (v2b ^ s_w3b[o]))
              + __popc(m2c & (v2c ^ s_w3c[o]));
        int s = mc2 - 2 * d;
        v3 |= (uint32_t)(s > 0)  << o;
        m3 |= (uint32_t)(s != 0) << o;
    }

    // fc1: 16 -> 8, ternary
    const int mc3 = __popc(m3);
    uint32_t v4 = 0, m4 = 0;
    #pragma unroll
    for (int o = 0; o < 8; o++) {
        int d = __popc(m3 & (v3 ^ s_wfc1[o]));
        int s = mc3 - 2 * d;
        v4 |= (uint32_t)(s > 0)  << o;
        m4 |= (uint32_t)(s != 0) << o;
    }

    // fc2: 8 -> 1, integer output
    int d5  = __popc(m4 & (v4 ^ s_wfc2));
    int res = __popc(m4) - 2 * d5;

    const int img = blockIdx.x * 128 + wrp * 32 + lane;
    if (img < B) out[img] = (float)res;
}

extern "C" void kernel_launch(void* const* d_in, const int* in_sizes, int n_in,
                              void* d_out, int out_size) {
    const float* x    = (const float*)d_in[0];
    const float* w1   = (const float*)d_in[1];
    const float* w2   = (const float*)d_in[2];
    const float* w3   = (const float*)d_in[3];
    const float* wfc1 = (const float*)d_in[4];
    const float* wfc2 = (const float*)d_in[5];
    float* out = (float*)d_out;

    int B = in_sizes[0] / 225;                 // x is [B,1,15,15]
    int blocks = (B + 127) / 128;              // 128 images/block, 4 warps
    bnn_kernel<<<blocks, 128>>>(x, w1, w2, w3, wfc1, wfc2, out, B);
}